// round 15
// baseline (speedup 1.0000x reference)
#include <cuda_runtime.h>

#define CH 32
#define SEGS 33
#define NMAX 50000
#define EMAX 200000
#define FULL 0xffffffffu
#define NBLK 592
#define NTHR 128
#define NWARP (NBLK * 4)
#define NT (NBLK * NTHR)
#define ACH 8
#define ER 3                    // edge rounds: ceil(200000 / 75776)
#define TBLK (8 * SEGS)         // 264 table-build blocks (s=blk>>3, chunk=blk&7)

typedef unsigned long long ull;

// ---- device-global scratch (zero-init; self-cleaned every launch) ----
__device__ ull   g_AB[SEGS * 1024];   // [0,512)=PA pairs, [512,1024)=PB pairs per seg
__device__ float g_aA[SEGS * 32], g_aB[SEGS * 32];
__device__ int   g_ecnt[SEGS];        // bucket cursors (zero at entry)
__device__ int   g_bar, g_done;       // grid barrier (monotonic) + completion counter
__device__ __align__(16) int2 g_ebuckp[SEGS * EMAX];  // {row<<16|col, t_bits}
__device__ __align__(16) float2 g_cts[SEGS * NMAX];   // (count, sum_t), zero at entry

// ---------------------------------------------------------------------------
__device__ __forceinline__ int bp_sort(const float* __restrict__ W,
                                       const float* __restrict__ Bv,
                                       int lane, float* sorted) {
    float w = W[lane], b = Bv[lane];
    float p = (w != 0.0f) ? (-b / w) : -1.0f;
    bool valid = (p > 0.0f && p < 1.0f);
    unsigned vm = __ballot_sync(FULL, valid);
    int c = __popc(vm);
    int rank = 0;
    #pragma unroll
    for (int i = 0; i < 32; i++) {
        float pi = __shfl_sync(FULL, p, i);
        bool vi = (vm >> i) & 1u;
        if (vi && (pi < p || (pi == p && i < lane))) rank++;
    }
    if (valid) sorted[rank] = p;
    __syncwarp();
    return c;
}

__device__ __forceinline__ void grid_bar(int tid, int target) {
    __syncthreads();
    if (tid == 0) {
        __threadfence();
        atomicAdd(&g_bar, 1);
        while (atomicAdd(&g_bar, 0) < target) __nanosleep(64);
        __threadfence();
    }
    __syncthreads();
}

// ---------------------------------------------------------------------------
// Single persistent kernel:
//  phase 0: tables + bucketing + angle scatter
//  barrier 1 -> phase 1a: angle expansion, PLAIN STORES (out initializer)
//  barrier 2 -> phase 1b: edge compute (red-adds) -> self-clean.
// ---------------------------------------------------------------------------
__global__ void __launch_bounds__(NTHR, 4)
k_all(const float* __restrict__ x,
      const int* __restrict__ ei, const float* __restrict__ ea,
      const int* __restrict__ ai, const float* __restrict__ ang,
      const float* __restrict__ eW1, const float* __restrict__ eb1,
      const float* __restrict__ eW2, const float* __restrict__ eb2,
      const float* __restrict__ aW1, const float* __restrict__ ab1,
      const float* __restrict__ aW2, const float* __restrict__ ab2,
      float* __restrict__ out, int E, int A, int N) {
    __shared__ float sbe[33], sba[33];
    __shared__ int snbe, snba;
    __shared__ float w1[32], b1[32];
    __shared__ int bcnt[SEGS], gbase[SEGS], cpre[SEGS + 1];
    __shared__ __align__(16) float stage[4][NTHR];
    __shared__ __align__(16) float stres[4][NTHR];
    __shared__ __align__(16) float tst[4][4];     // per-warp staged t values
    __shared__ float2 scts[ACH][NTHR];

    int tid = threadIdx.x, lane = tid & 31, warp = tid >> 5;
    int blk = blockIdx.x;
    int q_my = lane >> 3, sub = lane & 7;

    // ---- local breakpoints + weight copies ----
    if (warp == 0) {
        int c = bp_sort(eW1, eb1, lane, sbe);
        if (lane == 0) snbe = c;
    } else if (warp == 1) {
        int c = bp_sort(aW1, ab1, lane, sba);
        if (lane == 0) snba = c;
    } else if (warp == 2) {
        w1[lane] = eW1[lane];
        b1[lane] = eb1[lane];
    }
    if (tid < SEGS) bcnt[tid] = 0;
    __syncthreads();
    int nbe = snbe, nba = snba;

    // ================= Phase 0a: table build =================
    if (blk < TBLK) {
        int s = blk >> 3, chunk = blk & 7;
        if (s <= nbe) {
            float lo = (s == 0) ? 0.0f : sbe[s - 1];
            float hi = (s == nbe) ? 1.0f : sbe[s];
            float trep = 0.5f * (lo + hi);
            int io = chunk * NTHR + tid;
            float a = eb2[io], b = 0.0f;
            #pragma unroll
            for (int k = 0; k < 32; k++) {
                if (w1[k] * trep + b1[k] > 0.0f) {
                    float w2 = __ldg(eW2 + k * 1024 + io);
                    a = fmaf(b1[k], w2, a);
                    b = fmaf(w1[k], w2, b);
                }
            }
            int i = io >> 5, o = io & 31;
            int pa = s * 2048 + (i >> 1) * 64 + o * 2 + (i & 1);
            float* ABf = (float*)g_AB;
            ABf[pa] = a;
            ABf[pa + 1024] = b;
        }
    } else if (blk == TBLK) {
        int ca = nba, ns = ca + 1;
        for (int idx = tid; idx < ns * 32; idx += NTHR) {
            int s2 = idx >> 5, o = idx & 31;
            float lo = (s2 == 0) ? 0.0f : sba[s2 - 1];
            float hi = (s2 == ca) ? 1.0f : sba[s2];
            float trep = 0.5f * (lo + hi);
            float a = ab2[o], b = 0.0f;
            #pragma unroll
            for (int k = 0; k < 32; k++) {
                float w = aW1[k], bb = ab1[k];
                if (w * trep + bb > 0.0f) {
                    float w2 = aW2[k * 32 + o];
                    a = fmaf(bb, w2, a);
                    b = fmaf(w, w2, b);
                }
            }
            g_aA[idx] = a;
            g_aB[idx] = b;
        }
    }

    // ================= Phase 0b: edge bucketing (block-aggregated) ==========
    int segR[ER], rnkR[ER];
    int2 pay[ER];
    #pragma unroll
    for (int r = 0; r < ER; r++) {
        int i = blk * NTHR + tid + r * NT;
        segR[r] = -1;
        if (i < E) {
            float t = __ldg(ea + i);
            int seg = 0;
            for (int k = 0; k < nbe; k++) seg += (sbe[k] <= t) ? 1 : 0;
            segR[r] = seg;
            rnkR[r] = atomicAdd(&bcnt[seg], 1);
            unsigned rc = ((unsigned)__ldg(ei + i) << 16) | (unsigned)__ldg(ei + E + i);
            pay[r] = make_int2((int)rc, __float_as_int(t));
        }
    }
    __syncthreads();
    if (tid <= nbe) gbase[tid] = atomicAdd(&g_ecnt[tid], bcnt[tid]);
    __syncthreads();
    #pragma unroll
    for (int r = 0; r < ER; r++) {
        if (segR[r] >= 0)
            g_ebuckp[segR[r] * EMAX + gbase[segR[r]] + rnkR[r]] = pay[r];
    }

    // ================= Phase 0c: angle scatter (vector red) =================
    for (int i = blk * NTHR + tid; i < A; i += NT) {
        float ta = __ldg(ang + i);
        int j = __ldg(ai + A + i);
        int sa2 = 0;
        for (int k = 0; k < nba; k++) sa2 += (sba[k] <= ta) ? 1 : 0;
        float* p = (float*)&g_cts[sa2 * NMAX + j];
        asm volatile("red.global.add.v2.f32 [%0], {%1, %2};"
                     :: "l"(p), "f"(1.0f), "f"(ta) : "memory");
    }

    // ================= grid barrier 1 =================
    grid_bar(tid, NBLK);

    // ---- prefix sums over bucket counts ----
    if (tid == 0) {
        int acc = 0;
        for (int s2 = 0; s2 <= nbe; s2++) { cpre[s2] = acc; acc += g_ecnt[s2]; }
        cpre[nbe + 1] = acc;
    }

    // ================= Phase 1a: angle expansion, PLAIN STORES ==============
    int na = nba + 1;
    int j0 = blk * NTHR;
    int jt = j0 + tid;
    float2 z2 = make_float2(0.f, 0.f);
    if (j0 < N) {
        int ce = na < ACH ? na : ACH;
        for (int s2 = 0; s2 < ce; s2++)
            scts[s2][tid] = (jt < N) ? g_cts[s2 * NMAX + jt] : z2;
        __syncthreads();
        for (int s2 = 0; s2 < ce; s2++)          // self-clean staged slices
            if (jt < N) g_cts[s2 * NMAX + jt] = z2;

        float aAr[ACH], aBr[ACH];
        for (int s2 = 0; s2 < ce; s2++) {
            aAr[s2] = g_aA[s2 * 32 + lane];
            aBr[s2] = g_aB[s2 * 32 + lane];
        }
        for (int g = 0; g < 8; g++) {
            int nb0 = warp * 32 + g * 4;
            #pragma unroll
            for (int q = 0; q < 4; q++) {
                float acc = 0.0f;
                for (int s2 = 0; s2 < ce; s2++) {
                    float2 ct = scts[s2][nb0 + q];
                    acc = fmaf(ct.x, aAr[s2], acc);
                    acc = fmaf(ct.y, aBr[s2], acc);
                }
                for (int s2 = ACH; s2 < na; s2++) {
                    int jn = j0 + nb0 + q;
                    float2 ct = (jn < N) ? g_cts[s2 * NMAX + jn] : z2;
                    acc = fmaf(ct.x, g_aA[s2 * 32 + lane], acc);
                    acc = fmaf(ct.y, g_aB[s2 * 32 + lane], acc);
                }
                stres[warp][q * 32 + lane] = acc;
            }
            __syncwarp();
            int node = j0 + nb0 + q_my;
            if (node < N) {
                float4 v = ((const float4*)stres[warp])[lane];
                ((float4*)(out + node * 32))[sub] = v;   // plain ST: initializer
            }
            __syncwarp();
        }
        for (int s2 = ACH; s2 < na; s2++)        // clean overflow segments
            if (jt < N) g_cts[s2 * NMAX + jt] = z2;
    }

    // ================= grid barrier 2 (out fully initialized) ===============
    grid_bar(tid, 2 * NBLK);

    // ================= Phase 1b: edge compute (contiguous partition) =========
    {
        int ns = nbe + 1;
        int Etot = cpre[ns];
        int gwarp = blk * 4 + warp;
        int Tw = (Etot + NWARP - 1) / NWARP;
        int lo = gwarp * Tw;
        int hi = lo + Tw; if (hi > Etot) hi = Etot;
        int s = 0;
        const float4* __restrict__ x4 = (const float4*)x;

        while (lo < hi) {
            while (cpre[s + 1] <= lo) s++;
            int seg_end = cpre[s + 1] < hi ? cpre[s + 1] : hi;
            int run = seg_end - lo;
            int local = lo - cpre[s];

            ull abA[16], abB[16];
            const ull* Tt = g_AB + s * 1024;
            #pragma unroll
            for (int k = 0; k < 16; k++) {
                abA[k] = Tt[k * 32 + lane];
                abB[k] = Tt[512 + k * 32 + lane];
            }
            const int2* __restrict__ buck = g_ebuckp + s * EMAX;
            int idx = local, end = local + run, last = end - 1;
            int pe = idx + q_my; if (pe > last) pe = last;
            int2 pm = __ldg(buck + pe);
            float4 xf = __ldg(x4 + ((unsigned)pm.x & 0xffffu) * 8 + sub);

            while (idx < end) {
                ((float4*)stage[warp])[lane] = xf;
                if (sub == 0) tst[warp][q_my] = __int_as_float(pm.y);
                __syncwarp();
                int rowc = (int)((unsigned)pm.x >> 16);
                bool mine = (idx + q_my < end);
                idx += 4;
                if (idx < end) {
                    pe = idx + q_my; if (pe > last) pe = last;
                    pm = __ldg(buck + pe);
                    xf = __ldg(x4 + ((unsigned)pm.x & 0xffffu) * 8 + sub);
                }

                const ulonglong2* __restrict__ sv = (const ulonglong2*)stage[warp];
                float4 tq = *((const float4*)tst[warp]);   // LDS.128 broadcast
                ull aA0 = 0, aB0 = 0, aA1 = 0, aB1 = 0, aA2 = 0, aB2 = 0, aA3 = 0, aB3 = 0;
                #pragma unroll
                for (int j = 0; j < 8; j++) {
                    ulonglong2 v0 = sv[j], v1 = sv[8 + j], v2 = sv[16 + j], v3 = sv[24 + j];
                    asm("fma.rn.f32x2 %0, %1, %2, %0;" : "+l"(aA0) : "l"(v0.x), "l"(abA[2 * j]));
                    asm("fma.rn.f32x2 %0, %1, %2, %0;" : "+l"(aB0) : "l"(v0.x), "l"(abB[2 * j]));
                    asm("fma.rn.f32x2 %0, %1, %2, %0;" : "+l"(aA1) : "l"(v1.x), "l"(abA[2 * j]));
                    asm("fma.rn.f32x2 %0, %1, %2, %0;" : "+l"(aB1) : "l"(v1.x), "l"(abB[2 * j]));
                    asm("fma.rn.f32x2 %0, %1, %2, %0;" : "+l"(aA2) : "l"(v2.x), "l"(abA[2 * j]));
                    asm("fma.rn.f32x2 %0, %1, %2, %0;" : "+l"(aB2) : "l"(v2.x), "l"(abB[2 * j]));
                    asm("fma.rn.f32x2 %0, %1, %2, %0;" : "+l"(aA3) : "l"(v3.x), "l"(abA[2 * j]));
                    asm("fma.rn.f32x2 %0, %1, %2, %0;" : "+l"(aB3) : "l"(v3.x), "l"(abB[2 * j]));
                    asm("fma.rn.f32x2 %0, %1, %2, %0;" : "+l"(aA0) : "l"(v0.y), "l"(abA[2 * j + 1]));
                    asm("fma.rn.f32x2 %0, %1, %2, %0;" : "+l"(aB0) : "l"(v0.y), "l"(abB[2 * j + 1]));
                    asm("fma.rn.f32x2 %0, %1, %2, %0;" : "+l"(aA1) : "l"(v1.y), "l"(abA[2 * j + 1]));
                    asm("fma.rn.f32x2 %0, %1, %2, %0;" : "+l"(aB1) : "l"(v1.y), "l"(abB[2 * j + 1]));
                    asm("fma.rn.f32x2 %0, %1, %2, %0;" : "+l"(aA2) : "l"(v2.y), "l"(abA[2 * j + 1]));
                    asm("fma.rn.f32x2 %0, %1, %2, %0;" : "+l"(aB2) : "l"(v2.y), "l"(abB[2 * j + 1]));
                    asm("fma.rn.f32x2 %0, %1, %2, %0;" : "+l"(aA3) : "l"(v3.y), "l"(abA[2 * j + 1]));
                    asm("fma.rn.f32x2 %0, %1, %2, %0;" : "+l"(aB3) : "l"(v3.y), "l"(abB[2 * j + 1]));
                }
                float alo, ahi, blo, bhi;
                asm("mov.b64 {%0, %1}, %2;" : "=f"(alo), "=f"(ahi) : "l"(aA0));
                asm("mov.b64 {%0, %1}, %2;" : "=f"(blo), "=f"(bhi) : "l"(aB0));
                stres[warp][lane] = fmaf(tq.x, blo + bhi, alo + ahi);
                asm("mov.b64 {%0, %1}, %2;" : "=f"(alo), "=f"(ahi) : "l"(aA1));
                asm("mov.b64 {%0, %1}, %2;" : "=f"(blo), "=f"(bhi) : "l"(aB1));
                stres[warp][32 + lane] = fmaf(tq.y, blo + bhi, alo + ahi);
                asm("mov.b64 {%0, %1}, %2;" : "=f"(alo), "=f"(ahi) : "l"(aA2));
                asm("mov.b64 {%0, %1}, %2;" : "=f"(blo), "=f"(bhi) : "l"(aB2));
                stres[warp][64 + lane] = fmaf(tq.z, blo + bhi, alo + ahi);
                asm("mov.b64 {%0, %1}, %2;" : "=f"(alo), "=f"(ahi) : "l"(aA3));
                asm("mov.b64 {%0, %1}, %2;" : "=f"(blo), "=f"(bhi) : "l"(aB3));
                stres[warp][96 + lane] = fmaf(tq.w, blo + bhi, alo + ahi);
                __syncwarp();

                if (mine) {
                    float4 v = ((const float4*)stres[warp])[lane];
                    float* dst = out + rowc * 32 + sub * 4;
                    asm volatile("red.global.add.v4.f32 [%0], {%1, %2, %3, %4};"
                                 :: "l"(dst), "f"(v.x), "f"(v.y), "f"(v.z), "f"(v.w)
                                 : "memory");
                }
                __syncwarp();
            }
            lo = seg_end;
        }
    }

    // ================= self-clean for next replay =================
    __syncthreads();
    if (tid == 0) {
        __threadfence();
        int v = atomicAdd(&g_done, 1);
        if (v == NBLK - 1) {
            g_done = 0;
            g_bar = 0;
            #pragma unroll
            for (int s2 = 0; s2 < SEGS; s2++) g_ecnt[s2] = 0;
        }
    }
}

// ---------------------------------------------------------------------------
extern "C" void kernel_launch(void* const* d_in, const int* in_sizes, int n_in,
                              void* d_out, int out_size) {
    const float* x   = (const float*)d_in[0];
    const int*   ei  = (const int*)d_in[1];
    const float* ea  = (const float*)d_in[2];
    const int*   ai  = (const int*)d_in[3];
    const float* ang = (const float*)d_in[4];
    const float* eW1 = (const float*)d_in[5];
    const float* eb1 = (const float*)d_in[6];
    const float* eW2 = (const float*)d_in[7];
    const float* eb2 = (const float*)d_in[8];
    const float* aW1 = (const float*)d_in[9];
    const float* ab1 = (const float*)d_in[10];
    const float* aW2 = (const float*)d_in[11];
    const float* ab2 = (const float*)d_in[12];
    float* out = (float*)d_out;

    int N = in_sizes[0] / CH;
    int E = in_sizes[1] / 2;
    int A = in_sizes[3] / 3;

    k_all<<<NBLK, NTHR>>>(x, ei, ea, ai, ang, eW1, eb1, eW2, eb2,
                          aW1, ab1, aW2, ab2, out, E, A, N);
}

// round 16
// speedup vs baseline: 1.0910x; 1.0910x over previous
#include <cuda_runtime.h>

#define CH 32
#define SEGS 33
#define NMAX 50000
#define EMAX 200000
#define FULL 0xffffffffu
#define NBLK 592
#define NTHR 128
#define NWARP (NBLK * 4)
#define NT (NBLK * NTHR)
#define ACH 8
#define ER 3                    // edge rounds: ceil(200000 / 75776)
#define TBLK (8 * SEGS)         // 264 table-build blocks (s=blk>>3, chunk=blk&7)

typedef unsigned long long ull;

// ---- device-global scratch (zero-init; self-cleaned every launch) ----
__device__ ull   g_AB[SEGS * 1024];   // [0,512)=PA pairs, [512,1024)=PB pairs per seg
__device__ float g_aA[SEGS * 32], g_aB[SEGS * 32];
__device__ int   g_ecnt[SEGS];        // bucket cursors (zero at entry)
__device__ int   g_bar, g_done;       // grid barrier + completion counter
__device__ __align__(16) int2 g_ebuckp[SEGS * EMAX];  // {row<<16|col, t_bits}
__device__ __align__(16) float2 g_cts[SEGS * NMAX];   // (count, sum_t), zero at entry

// ---------------------------------------------------------------------------
__device__ __forceinline__ int bp_sort(const float* __restrict__ W,
                                       const float* __restrict__ Bv,
                                       int lane, float* sorted) {
    float w = W[lane], b = Bv[lane];
    float p = (w != 0.0f) ? (-b / w) : -1.0f;
    bool valid = (p > 0.0f && p < 1.0f);
    unsigned vm = __ballot_sync(FULL, valid);
    int c = __popc(vm);
    int rank = 0;
    #pragma unroll
    for (int i = 0; i < 32; i++) {
        float pi = __shfl_sync(FULL, p, i);
        bool vi = (vm >> i) & 1u;
        if (vi && (pi < p || (pi == p && i < lane))) rank++;
    }
    if (valid) sorted[rank] = p;
    __syncwarp();
    return c;
}

// ---------------------------------------------------------------------------
// Single persistent kernel (R14 base): [phase 0: tables + out-zeroing +
// bucketing + angle scatter] -> grid barrier -> [phase 1: angle expansion
// (red) + edge compute (red, t folded via smem broadcast)] -> self-clean.
// ---------------------------------------------------------------------------
__global__ void __launch_bounds__(NTHR, 4)
k_all(const float* __restrict__ x,
      const int* __restrict__ ei, const float* __restrict__ ea,
      const int* __restrict__ ai, const float* __restrict__ ang,
      const float* __restrict__ eW1, const float* __restrict__ eb1,
      const float* __restrict__ eW2, const float* __restrict__ eb2,
      const float* __restrict__ aW1, const float* __restrict__ ab1,
      const float* __restrict__ aW2, const float* __restrict__ ab2,
      float* __restrict__ out, int E, int A, int N) {
    __shared__ float sbe[33], sba[33];
    __shared__ int snbe, snba;
    __shared__ float w1[32], b1[32];
    __shared__ int bcnt[SEGS], gbase[SEGS], cpre[SEGS + 1];
    __shared__ __align__(16) float stage[4][NTHR];
    __shared__ __align__(16) float stres[4][NTHR];
    __shared__ __align__(16) float tst[4][4];     // per-warp staged t values
    __shared__ float2 scts[ACH][NTHR];

    int tid = threadIdx.x, lane = tid & 31, warp = tid >> 5;
    int blk = blockIdx.x;
    int q_my = lane >> 3, sub = lane & 7;

    // ---- local breakpoints + weight copies ----
    if (warp == 0) {
        int c = bp_sort(eW1, eb1, lane, sbe);
        if (lane == 0) snbe = c;
    } else if (warp == 1) {
        int c = bp_sort(aW1, ab1, lane, sba);
        if (lane == 0) snba = c;
    } else if (warp == 2) {
        w1[lane] = eW1[lane];
        b1[lane] = eb1[lane];
    }
    if (tid < SEGS) bcnt[tid] = 0;
    __syncthreads();
    int nbe = snbe, nba = snba;

    // ================= Phase 0a: table build =================
    if (blk < TBLK) {
        int s = blk >> 3, chunk = blk & 7;
        if (s <= nbe) {
            float lo = (s == 0) ? 0.0f : sbe[s - 1];
            float hi = (s == nbe) ? 1.0f : sbe[s];
            float trep = 0.5f * (lo + hi);
            int io = chunk * NTHR + tid;
            float a = eb2[io], b = 0.0f;
            #pragma unroll
            for (int k = 0; k < 32; k++) {
                if (w1[k] * trep + b1[k] > 0.0f) {
                    float w2 = __ldg(eW2 + k * 1024 + io);
                    a = fmaf(b1[k], w2, a);
                    b = fmaf(w1[k], w2, b);
                }
            }
            int i = io >> 5, o = io & 31;
            int pa = s * 2048 + (i >> 1) * 64 + o * 2 + (i & 1);
            float* ABf = (float*)g_AB;
            ABf[pa] = a;
            ABf[pa + 1024] = b;
        }
    } else if (blk == TBLK) {
        int ca = nba, ns = ca + 1;
        for (int idx = tid; idx < ns * 32; idx += NTHR) {
            int s2 = idx >> 5, o = idx & 31;
            float lo = (s2 == 0) ? 0.0f : sba[s2 - 1];
            float hi = (s2 == ca) ? 1.0f : sba[s2];
            float trep = 0.5f * (lo + hi);
            float a = ab2[o], b = 0.0f;
            #pragma unroll
            for (int k = 0; k < 32; k++) {
                float w = aW1[k], bb = ab1[k];
                if (w * trep + bb > 0.0f) {
                    float w2 = aW2[k * 32 + o];
                    a = fmaf(bb, w2, a);
                    b = fmaf(w, w2, b);
                }
            }
            g_aA[idx] = a;
            g_aB[idx] = b;
        }
    }

    // ================= Phase 0b: zero out =================
    {
        float4 z = make_float4(0.f, 0.f, 0.f, 0.f);
        int no = N * 8;
        float4* o4 = (float4*)out;
        for (int k2 = blk * NTHR + tid; k2 < no; k2 += NT) o4[k2] = z;
    }

    // ================= Phase 0c: edge bucketing (block-aggregated) ==========
    int segR[ER], rnkR[ER];
    int2 pay[ER];
    #pragma unroll
    for (int r = 0; r < ER; r++) {
        int i = blk * NTHR + tid + r * NT;
        segR[r] = -1;
        if (i < E) {
            float t = __ldg(ea + i);
            int seg = 0;
            for (int k = 0; k < nbe; k++) seg += (sbe[k] <= t) ? 1 : 0;
            segR[r] = seg;
            rnkR[r] = atomicAdd(&bcnt[seg], 1);
            unsigned rc = ((unsigned)__ldg(ei + i) << 16) | (unsigned)__ldg(ei + E + i);
            pay[r] = make_int2((int)rc, __float_as_int(t));
        }
    }
    __syncthreads();
    if (tid <= nbe) gbase[tid] = atomicAdd(&g_ecnt[tid], bcnt[tid]);
    __syncthreads();
    #pragma unroll
    for (int r = 0; r < ER; r++) {
        if (segR[r] >= 0)
            g_ebuckp[segR[r] * EMAX + gbase[segR[r]] + rnkR[r]] = pay[r];
    }

    // ================= Phase 0d: angle scatter (vector red) =================
    for (int i = blk * NTHR + tid; i < A; i += NT) {
        float ta = __ldg(ang + i);
        int j = __ldg(ai + A + i);
        int sa2 = 0;
        for (int k = 0; k < nba; k++) sa2 += (sba[k] <= ta) ? 1 : 0;
        float* p = (float*)&g_cts[sa2 * NMAX + j];
        asm volatile("red.global.add.v2.f32 [%0], {%1, %2};"
                     :: "l"(p), "f"(1.0f), "f"(ta) : "memory");
    }

    // ================= grid barrier (all NBLK blocks resident) ===============
    __syncthreads();
    if (tid == 0) {
        __threadfence();
        atomicAdd(&g_bar, 1);
        while (atomicAdd(&g_bar, 0) < NBLK) __nanosleep(64);
        __threadfence();
    }
    __syncthreads();

    // ---- prefix sums over bucket counts ----
    if (tid == 0) {
        int acc = 0;
        for (int s2 = 0; s2 <= nbe; s2++) { cpre[s2] = acc; acc += g_ecnt[s2]; }
        cpre[nbe + 1] = acc;
    }
    __syncthreads();

    // ================= Phase 1a: angle expansion (red) =================
    int na = nba + 1;
    int j0 = blk * NTHR;
    int jt = j0 + tid;
    float2 z2 = make_float2(0.f, 0.f);
    if (j0 < N) {
        int ce = na < ACH ? na : ACH;
        for (int s2 = 0; s2 < ce; s2++)
            scts[s2][tid] = (jt < N) ? g_cts[s2 * NMAX + jt] : z2;
        __syncthreads();
        for (int s2 = 0; s2 < ce; s2++)          // self-clean staged slices
            if (jt < N) g_cts[s2 * NMAX + jt] = z2;

        float aAr[ACH], aBr[ACH];
        for (int s2 = 0; s2 < ce; s2++) {
            aAr[s2] = g_aA[s2 * 32 + lane];
            aBr[s2] = g_aB[s2 * 32 + lane];
        }
        for (int g = 0; g < 8; g++) {
            int nb0 = warp * 32 + g * 4;
            #pragma unroll
            for (int q = 0; q < 4; q++) {
                float acc = 0.0f;
                for (int s2 = 0; s2 < ce; s2++) {
                    float2 ct = scts[s2][nb0 + q];
                    acc = fmaf(ct.x, aAr[s2], acc);
                    acc = fmaf(ct.y, aBr[s2], acc);
                }
                for (int s2 = ACH; s2 < na; s2++) {
                    int jn = j0 + nb0 + q;
                    float2 ct = (jn < N) ? g_cts[s2 * NMAX + jn] : z2;
                    acc = fmaf(ct.x, g_aA[s2 * 32 + lane], acc);
                    acc = fmaf(ct.y, g_aB[s2 * 32 + lane], acc);
                }
                stres[warp][q * 32 + lane] = acc;
            }
            __syncwarp();
            int node = j0 + nb0 + q_my;
            if (node < N) {
                float4 v = ((const float4*)stres[warp])[lane];
                float* dst = out + node * 32 + sub * 4;
                asm volatile("red.global.add.v4.f32 [%0], {%1, %2, %3, %4};"
                             :: "l"(dst), "f"(v.x), "f"(v.y), "f"(v.z), "f"(v.w)
                             : "memory");
            }
            __syncwarp();
        }
        for (int s2 = ACH; s2 < na; s2++)        // clean overflow segments
            if (jt < N) g_cts[s2 * NMAX + jt] = z2;
    }

    // ================= Phase 1b: edge compute (contiguous partition) =========
    {
        int ns = nbe + 1;
        int Etot = cpre[ns];
        int gwarp = blk * 4 + warp;
        int Tw = (Etot + NWARP - 1) / NWARP;
        int lo = gwarp * Tw;
        int hi = lo + Tw; if (hi > Etot) hi = Etot;
        int s = 0;
        const float4* __restrict__ x4 = (const float4*)x;

        while (lo < hi) {
            while (cpre[s + 1] <= lo) s++;
            int seg_end = cpre[s + 1] < hi ? cpre[s + 1] : hi;
            int run = seg_end - lo;
            int local = lo - cpre[s];

            ull abA[16], abB[16];
            const ull* Tt = g_AB + s * 1024;
            #pragma unroll
            for (int k = 0; k < 16; k++) {
                abA[k] = Tt[k * 32 + lane];
                abB[k] = Tt[512 + k * 32 + lane];
            }
            const int2* __restrict__ buck = g_ebuckp + s * EMAX;
            int idx = local, end = local + run, last = end - 1;
            int pe = idx + q_my; if (pe > last) pe = last;
            int2 pm = __ldg(buck + pe);
            float4 xf = __ldg(x4 + ((unsigned)pm.x & 0xffffu) * 8 + sub);

            while (idx < end) {
                ((float4*)stage[warp])[lane] = xf;
                if (sub == 0) tst[warp][q_my] = __int_as_float(pm.y);
                __syncwarp();
                int rowc = (int)((unsigned)pm.x >> 16);
                bool mine = (idx + q_my < end);
                idx += 4;
                if (idx < end) {
                    pe = idx + q_my; if (pe > last) pe = last;
                    pm = __ldg(buck + pe);
                    xf = __ldg(x4 + ((unsigned)pm.x & 0xffffu) * 8 + sub);
                }

                const ulonglong2* __restrict__ sv = (const ulonglong2*)stage[warp];
                float4 tq = *((const float4*)tst[warp]);   // LDS.128 broadcast
                ull aA0 = 0, aB0 = 0, aA1 = 0, aB1 = 0, aA2 = 0, aB2 = 0, aA3 = 0, aB3 = 0;
                #pragma unroll
                for (int j = 0; j < 8; j++) {
                    ulonglong2 v0 = sv[j], v1 = sv[8 + j], v2 = sv[16 + j], v3 = sv[24 + j];
                    asm("fma.rn.f32x2 %0, %1, %2, %0;" : "+l"(aA0) : "l"(v0.x), "l"(abA[2 * j]));
                    asm("fma.rn.f32x2 %0, %1, %2, %0;" : "+l"(aB0) : "l"(v0.x), "l"(abB[2 * j]));
                    asm("fma.rn.f32x2 %0, %1, %2, %0;" : "+l"(aA1) : "l"(v1.x), "l"(abA[2 * j]));
                    asm("fma.rn.f32x2 %0, %1, %2, %0;" : "+l"(aB1) : "l"(v1.x), "l"(abB[2 * j]));
                    asm("fma.rn.f32x2 %0, %1, %2, %0;" : "+l"(aA2) : "l"(v2.x), "l"(abA[2 * j]));
                    asm("fma.rn.f32x2 %0, %1, %2, %0;" : "+l"(aB2) : "l"(v2.x), "l"(abB[2 * j]));
                    asm("fma.rn.f32x2 %0, %1, %2, %0;" : "+l"(aA3) : "l"(v3.x), "l"(abA[2 * j]));
                    asm("fma.rn.f32x2 %0, %1, %2, %0;" : "+l"(aB3) : "l"(v3.x), "l"(abB[2 * j]));
                    asm("fma.rn.f32x2 %0, %1, %2, %0;" : "+l"(aA0) : "l"(v0.y), "l"(abA[2 * j + 1]));
                    asm("fma.rn.f32x2 %0, %1, %2, %0;" : "+l"(aB0) : "l"(v0.y), "l"(abB[2 * j + 1]));
                    asm("fma.rn.f32x2 %0, %1, %2, %0;" : "+l"(aA1) : "l"(v1.y), "l"(abA[2 * j + 1]));
                    asm("fma.rn.f32x2 %0, %1, %2, %0;" : "+l"(aB1) : "l"(v1.y), "l"(abB[2 * j + 1]));
                    asm("fma.rn.f32x2 %0, %1, %2, %0;" : "+l"(aA2) : "l"(v2.y), "l"(abA[2 * j + 1]));
                    asm("fma.rn.f32x2 %0, %1, %2, %0;" : "+l"(aB2) : "l"(v2.y), "l"(abB[2 * j + 1]));
                    asm("fma.rn.f32x2 %0, %1, %2, %0;" : "+l"(aA3) : "l"(v3.y), "l"(abA[2 * j + 1]));
                    asm("fma.rn.f32x2 %0, %1, %2, %0;" : "+l"(aB3) : "l"(v3.y), "l"(abB[2 * j + 1]));
                }
                float alo, ahi, blo, bhi;
                asm("mov.b64 {%0, %1}, %2;" : "=f"(alo), "=f"(ahi) : "l"(aA0));
                asm("mov.b64 {%0, %1}, %2;" : "=f"(blo), "=f"(bhi) : "l"(aB0));
                stres[warp][lane] = fmaf(tq.x, blo + bhi, alo + ahi);
                asm("mov.b64 {%0, %1}, %2;" : "=f"(alo), "=f"(ahi) : "l"(aA1));
                asm("mov.b64 {%0, %1}, %2;" : "=f"(blo), "=f"(bhi) : "l"(aB1));
                stres[warp][32 + lane] = fmaf(tq.y, blo + bhi, alo + ahi);
                asm("mov.b64 {%0, %1}, %2;" : "=f"(alo), "=f"(ahi) : "l"(aA2));
                asm("mov.b64 {%0, %1}, %2;" : "=f"(blo), "=f"(bhi) : "l"(aB2));
                stres[warp][64 + lane] = fmaf(tq.z, blo + bhi, alo + ahi);
                asm("mov.b64 {%0, %1}, %2;" : "=f"(alo), "=f"(ahi) : "l"(aA3));
                asm("mov.b64 {%0, %1}, %2;" : "=f"(blo), "=f"(bhi) : "l"(aB3));
                stres[warp][96 + lane] = fmaf(tq.w, blo + bhi, alo + ahi);
                __syncwarp();

                if (mine) {
                    float4 v = ((const float4*)stres[warp])[lane];
                    float* dst = out + rowc * 32 + sub * 4;
                    asm volatile("red.global.add.v4.f32 [%0], {%1, %2, %3, %4};"
                                 :: "l"(dst), "f"(v.x), "f"(v.y), "f"(v.z), "f"(v.w)
                                 : "memory");
                }
                __syncwarp();
            }
            lo = seg_end;
        }
    }

    // ================= self-clean for next replay =================
    __syncthreads();
    if (tid == 0) {
        __threadfence();
        int v = atomicAdd(&g_done, 1);
        if (v == NBLK - 1) {
            g_done = 0;
            g_bar = 0;
            #pragma unroll
            for (int s2 = 0; s2 < SEGS; s2++) g_ecnt[s2] = 0;
        }
    }
}

// ---------------------------------------------------------------------------
extern "C" void kernel_launch(void* const* d_in, const int* in_sizes, int n_in,
                              void* d_out, int out_size) {
    const float* x   = (const float*)d_in[0];
    const int*   ei  = (const int*)d_in[1];
    const float* ea  = (const float*)d_in[2];
    const int*   ai  = (const int*)d_in[3];
    const float* ang = (const float*)d_in[4];
    const float* eW1 = (const float*)d_in[5];
    const float* eb1 = (const float*)d_in[6];
    const float* eW2 = (const float*)d_in[7];
    const float* eb2 = (const float*)d_in[8];
    const float* aW1 = (const float*)d_in[9];
    const float* ab1 = (const float*)d_in[10];
    const float* aW2 = (const float*)d_in[11];
    const float* ab2 = (const float*)d_in[12];
    float* out = (float*)d_out;

    int N = in_sizes[0] / CH;
    int E = in_sizes[1] / 2;
    int A = in_sizes[3] / 3;

    k_all<<<NBLK, NTHR>>>(x, ei, ea, ai, ang, eW1, eb1, eW2, eb2,
                          aW1, ab1, aW2, ab2, out, E, A, N);
}